// round 5
// baseline (speedup 1.0000x reference)
#include <cuda_runtime.h>
#include <cstdint>

// Problem constants
#define CCH    384
#define NPIX   1024          // 32*32
#define NIMG   16            // only first n=16 rows matter
#define KTOP   20
#define PTOT   96
#define NREM   76            // P - K
#define NUNSEL 1004          // 1024 - 20
#define NCHUNK 32
#define CHPER  12            // 384 / 32
#define NBATCH 3             // 12 channels / 4 per batch
#define NPERMBLK 16
#define ELEM_PER_PB 63       // 16*63 = 1008 >= 1004
#define PLROW  36            // padded row (even -> float2-aligned reads)
#define PLSZ   (PLROW * 34)
#define SCALE_F 4294967296.f // 2^32 fixed-point scale

// Scratch (device globals: no allocation allowed)
__device__ unsigned long long g_score[NIMG * NPIX];  // fixed-point sums (kB re-zeroes)
__device__ int g_invperm[NUNSEL];

__device__ __forceinline__ uint32_t rotl32(uint32_t x, int d) {
    return (x << d) | (x >> (32 - d));
}

// Threefry-2x32, 20 rounds (matches JAX threefry2x32_p)
__device__ __forceinline__ void threefry2x32(uint32_t k0, uint32_t k1,
                                             uint32_t x0, uint32_t x1,
                                             uint32_t& o0, uint32_t& o1) {
    uint32_t k2 = k0 ^ k1 ^ 0x1BD11BDAu;
#define TF_RND(r) { x0 += x1; x1 = rotl32(x1, (r)); x1 ^= x0; }
    x0 += k0; x1 += k1;
    TF_RND(13) TF_RND(15) TF_RND(26) TF_RND(6)
    x0 += k1; x1 += k2 + 1u;
    TF_RND(17) TF_RND(29) TF_RND(16) TF_RND(24)
    x0 += k2; x1 += k0 + 2u;
    TF_RND(13) TF_RND(15) TF_RND(26) TF_RND(6)
    x0 += k0; x1 += k1 + 3u;
    TF_RND(17) TF_RND(29) TF_RND(16) TF_RND(24)
    x0 += k1; x1 += k2 + 4u;
    TF_RND(13) TF_RND(15) TF_RND(26) TF_RND(6)
    x0 += k2; x1 += k0 + 5u;
#undef TF_RND
    o0 = x0; o1 = x1;
}

// ---------------------------------------------------------------------------
// Kernel A: blocks [0,16): JAX permutation inverse map.
//           blocks [16, 16+512): fused depthwise-3x3 + pointwise, 12 channels
//           per block, batched MLP-4 prefetch, single-buffer 4-plane smem,
//           int64 fixed-point RED into g_score (deterministic).
// ---------------------------------------------------------------------------
__global__ __launch_bounds__(256)
void patch_vote_kA(const float* __restrict__ feature,
                   const float* __restrict__ dww,
                   const float* __restrict__ pww) {
    int tid = threadIdx.x;

    if (blockIdx.x < NPERMBLK) {
        // ---- permutation block (verified exact) ----
        __shared__ __align__(16) uint32_t bits[NUNSEL];   // 1004 = 251 * 4
        uint32_t s0, s1;
        threefry2x32(0u, 42u, 0u, 1u, s0, s1);
        for (int i = tid; i < NUNSEL; i += 256) {
            uint32_t b1, b2;
            threefry2x32(s0, s1, 0u, (uint32_t)i, b1, b2);
            bits[i] = b1 ^ b2;
        }
        __syncthreads();

        int e = tid >> 2, part = tid & 3;
        int idx = blockIdx.x * ELEM_PER_PB + e;
        int rank = 0;
        bool valid = (e < ELEM_PER_PB) && (idx < NUNSEL);
        if (valid) {
            uint32_t bi = bits[idx];
            int q4b = part * 63;
            int q4e = q4b + 63; if (q4e > 251) q4e = 251;
            const uint4* b4 = reinterpret_cast<const uint4*>(bits);
            for (int q4 = q4b; q4 < q4e; q4++) {
                uint4 v = b4[q4];
                int q = q4 * 4;
                rank += (v.x < bi) || (v.x == bi && (q    ) < idx);
                rank += (v.y < bi) || (v.y == bi && (q + 1) < idx);
                rank += (v.z < bi) || (v.z == bi && (q + 2) < idx);
                rank += (v.w < bi) || (v.w == bi && (q + 3) < idx);
            }
        }
        rank += __shfl_xor_sync(0xffffffffu, rank, 1);
        rank += __shfl_xor_sync(0xffffffffu, rank, 2);
        if (valid && part == 0)
            g_invperm[idx] = (rank < NREM) ? rank : -1;
        return;
    }

    // ---- conv block ----
    int id    = blockIdx.x - NPERMBLK;
    int img   = id >> 5;          // / NCHUNK
    int chunk = id & 31;
    int c0    = chunk * CHPER;

    __shared__ __align__(16) float planes[4][PLSZ];
    __shared__ float wsm[CHPER * 10];

    for (int i = tid; i < 4 * PLSZ; i += 256)
        (&planes[0][0])[i] = 0.f;
    for (int i = tid; i < CHPER * 10; i += 256) {
        int ch = i / 10, k = i - ch * 10;
        wsm[i] = (k < 9) ? __ldg(dww + (size_t)(c0 + ch) * 9 + k)
                         : __ldg(pww + c0 + ch);
    }

    // 2x2 output tile per thread
    int tx = tid & 15, ty = tid >> 4;
    int px = tx * 2, py = ty * 2;

    // float4 global load -> smem mapping
    int lp = tid * 4;
    int ly = lp >> 5, lx = lp & 31;
    int dstoff = (ly + 1) * PLROW + lx + 1;

    const float4* f4 = reinterpret_cast<const float4*>(
        feature + ((size_t)img * CCH + c0) * NPIX);

    float4 v0 = f4[0 * 256 + tid], v1 = f4[1 * 256 + tid];
    float4 v2 = f4[2 * 256 + tid], v3 = f4[3 * 256 + tid];
    __syncthreads();                       // zero-init + weights complete

    float acc00 = 0.f, acc01 = 0.f, acc10 = 0.f, acc11 = 0.f;

#pragma unroll
    for (int b = 0; b < NBATCH; b++) {
        {
            float* d;
            d = &planes[0][dstoff]; d[0]=v0.x; d[1]=v0.y; d[2]=v0.z; d[3]=v0.w;
            d = &planes[1][dstoff]; d[0]=v1.x; d[1]=v1.y; d[2]=v1.z; d[3]=v1.w;
            d = &planes[2][dstoff]; d[0]=v2.x; d[1]=v2.y; d[2]=v2.z; d[3]=v2.w;
            d = &planes[3][dstoff]; d[0]=v3.x; d[1]=v3.y; d[2]=v3.z; d[3]=v3.w;
        }
        __syncthreads();                   // planes ready
        if (b + 1 < NBATCH) {              // prefetch next batch (MLP=4)
            int cb = (b + 1) * 4;
            v0 = f4[(cb + 0) * 256 + tid]; v1 = f4[(cb + 1) * 256 + tid];
            v2 = f4[(cb + 2) * 256 + tid]; v3 = f4[(cb + 3) * 256 + tid];
        }

#pragma unroll
        for (int j = 0; j < 4; j++) {
            const float* wp = wsm + (b * 4 + j) * 10;
            float w0 = wp[0], w1 = wp[1], w2 = wp[2];
            float w3 = wp[3], w4 = wp[4], w5 = wp[5];
            float w6 = wp[6], w7 = wp[7], w8 = wp[8];
            float pwc = wp[9];

            // 4x4 patch via 8 aligned float2 loads
            const float2* p2 = reinterpret_cast<const float2*>(
                &planes[j][py * PLROW + px]);
            float2 q00 = p2[0],  q01 = p2[1];
            float2 q10 = p2[18], q11 = p2[19];
            float2 q20 = p2[36], q21 = p2[37];
            float2 q30 = p2[54], q31 = p2[55];
            float a00=q00.x, a01=q00.y, a02=q01.x, a03=q01.y;
            float a10=q10.x, a11=q10.y, a12=q11.x, a13=q11.y;
            float a20=q20.x, a21=q20.y, a22=q21.x, a23=q21.y;
            float a30=q30.x, a31=q30.y, a32=q31.x, a33=q31.y;

            float s00 = w0*a00 + w1*a01 + w2*a02
                      + w3*a10 + w4*a11 + w5*a12
                      + w6*a20 + w7*a21 + w8*a22;
            float s01 = w0*a01 + w1*a02 + w2*a03
                      + w3*a11 + w4*a12 + w5*a13
                      + w6*a21 + w7*a22 + w8*a23;
            float s10 = w0*a10 + w1*a11 + w2*a12
                      + w3*a20 + w4*a21 + w5*a22
                      + w6*a30 + w7*a31 + w8*a32;
            float s11 = w0*a11 + w1*a12 + w2*a13
                      + w3*a21 + w4*a22 + w5*a23
                      + w6*a31 + w7*a32 + w8*a33;

            acc00 = fmaf(pwc, s00, acc00);
            acc01 = fmaf(pwc, s01, acc01);
            acc10 = fmaf(pwc, s10, acc10);
            acc11 = fmaf(pwc, s11, acc11);
        }
        if (b + 1 < NBATCH)
            __syncthreads();               // readers done before next store
    }

    // deterministic fixed-point accumulation
    unsigned long long* gs = g_score + (size_t)img * NPIX;
    atomicAdd(gs +  py      * 32 + px,
              (unsigned long long)(long long)__float2ll_rn(acc00 * SCALE_F));
    atomicAdd(gs +  py      * 32 + px + 1,
              (unsigned long long)(long long)__float2ll_rn(acc01 * SCALE_F));
    atomicAdd(gs + (py + 1) * 32 + px,
              (unsigned long long)(long long)__float2ll_rn(acc10 * SCALE_F));
    atomicAdd(gs + (py + 1) * 32 + px + 1,
              (unsigned long long)(long long)__float2ll_rn(acc11 * SCALE_F));
}

// ---------------------------------------------------------------------------
// Kernel B: 1 int64 load/thread, per-warp bitonic sort, threshold + warp-
//           parallel exact rank counting, ballot prefix for unselected,
//           invperm gather, float32 outputs. Re-zeroes g_score for replay.
// ---------------------------------------------------------------------------
__global__ __launch_bounds__(1024)
void patch_vote_kB(float* __restrict__ out) {
    int tid  = threadIdx.x;
    int img  = blockIdx.x;
    int lane = tid & 31, warp = tid >> 5;

    __shared__ unsigned long long scand[32 * 32];   // padded per-warp lists
    __shared__ int s_invp[NUNSEL];
    __shared__ int s_flag[NPIX];
    __shared__ int warpcnt[32];

    if (tid < NUNSEL) s_invp[tid] = g_invperm[tid];
    s_flag[tid] = 0;

    long long sc = (long long)g_score[(size_t)img * NPIX + tid];
    g_score[(size_t)img * NPIX + tid] = 0ull;       // reset for next replay

    // orderable key: (score + 2^53) << 10 | (1023 - pix); max == JAX order
    unsigned long long u = (unsigned long long)(sc + (1ll << 53));
    unsigned long long key = (u << 10) | (unsigned)(NPIX - 1 - tid);

    // per-warp bitonic sort, DESCENDING (lane 0 = max). Keys unique.
#pragma unroll
    for (int k = 2; k <= 32; k <<= 1) {
#pragma unroll
        for (int j = k >> 1; j > 0; j >>= 1) {
            unsigned long long o = __shfl_xor_sync(0xffffffffu, key, j);
            bool dirAsc  = ((lane & k) != 0);
            bool isLower = ((lane & j) == 0);
            bool takeMin = (dirAsc == isLower);
            key = takeMin ? (key < o ? key : o) : (key > o ? key : o);
        }
    }
    scand[(warp << 5) + lane] = (lane < KTOP) ? key : 0ull;  // pad with 0
    __syncthreads();

    // threshold S = max over warps of (warp's 20th key)  (computed per-warp,
    // no extra barrier: lane L reads warp-L's 20th entry)
    unsigned long long t = scand[(lane << 5) + (KTOP - 1)];
#pragma unroll
    for (int off = 16; off; off >>= 1) {
        unsigned long long o = __shfl_xor_sync(0xffffffffu, t, off);
        if (o > t) t = o;
    }
    unsigned long long S = t;   // uniform across warp

    // candidates = prefix of sorted lanes with key >= S (lane < 20)
    bool cand = (lane < KTOP) && (key >= S);
    unsigned cmask = __ballot_sync(0xffffffffu, cand);
    int m = __popc(cmask);      // candidates occupy lanes 0..m-1

    const unsigned long long* myl = scand + (lane << 5);  // lane L -> warp L list
    for (int i = 0; i < m; i++) {
        unsigned long long ck = __shfl_sync(0xffffffffu, key, i);
        int p = 0;                          // count entries > ck in my list
        p += (myl[p + 15] > ck) ? 16 : 0;
        p += (myl[p + 7]  > ck) ? 8  : 0;
        p += (myl[p + 3]  > ck) ? 4  : 0;
        p += (myl[p + 1]  > ck) ? 2  : 0;
        p += (myl[p]      > ck) ? 1  : 0;
        p += __shfl_xor_sync(0xffffffffu, p, 16);
        p += __shfl_xor_sync(0xffffffffu, p, 8);
        p += __shfl_xor_sync(0xffffffffu, p, 4);
        p += __shfl_xor_sync(0xffffffffu, p, 2);
        p += __shfl_xor_sync(0xffffffffu, p, 1);
        if (lane == i && p < KTOP) {        // exact global rank
            int pix = NPIX - 1 - (int)(key & 1023u);
            int X = pix & 31, Y = pix >> 5;
            float xo = (float)(X < 1 ? 1 : X);
            float yo = (float)(Y < 1 ? 1 : Y);
            out[              img * PTOT + p] = xo;
            out[NIMG * PTOT + img * PTOT + p] = yo;
            s_flag[pix] = 1;
        }
    }
    __syncthreads();

    // unselected positions via ballot prefix, gather through invperm
    bool sel = (s_flag[tid] != 0);
    unsigned bal = __ballot_sync(0xffffffffu, sel);
    if (lane == 0) warpcnt[warp] = __popc(bal);
    __syncthreads();
    int before = __popc(bal & ((1u << lane) - 1u));
    for (int w2 = 0; w2 < warp; w2++) before += warpcnt[w2];

    if (!sel) {
        int u2 = tid - before;          // position among unselected (0..1003)
        int j = s_invp[u2];
        if (j >= 0) {
            int X = tid & 31, Y = tid >> 5;
            float xo = (float)(X < 1 ? 1 : X);
            float yo = (float)(Y < 1 ? 1 : Y);
            out[              img * PTOT + KTOP + j] = xo;
            out[NIMG * PTOT + img * PTOT + KTOP + j] = yo;
        }
    }
}

extern "C" void kernel_launch(void* const* d_in, const int* in_sizes, int n_in,
                              void* d_out, int out_size) {
    const float* feature = (const float*)d_in[0];
    const float* dww     = (const float*)d_in[1];
    const float* pww     = (const float*)d_in[3];
    float* out = (float*)d_out;

    patch_vote_kA<<<NPERMBLK + NCHUNK * NIMG, 256>>>(feature, dww, pww);
    patch_vote_kB<<<NIMG, 1024>>>(out);
}

// round 6
// speedup vs baseline: 2.6334x; 2.6334x over previous
#include <cuda_runtime.h>
#include <cstdint>

// Problem constants
#define CCH    384
#define NPIX   1024          // 32*32
#define NIMG   16            // only first n=16 rows matter
#define KTOP   20
#define PTOT   96
#define NREM   76            // P - K
#define NUNSEL 1004          // 1024 - 20
#define NCHUNK 16
#define CHPER  24            // 384 / 16
#define NBATCH 6             // 24 channels / 4 per batch
#define NPERMBLK 16
#define ELEM_PER_PB 63       // 16*63 = 1008 >= 1004
#define PLROW  36            // padded row -> aligned float2 reads
#define PLSZ   (PLROW * 34)

// Scratch (device globals: no allocation allowed)
__device__ float g_partial[NCHUNK * NIMG * NPIX];   // [chunk][img][pix]
__device__ int   g_invperm[NUNSEL];

__device__ __forceinline__ uint32_t rotl32(uint32_t x, int d) {
    return (x << d) | (x >> (32 - d));
}

// Threefry-2x32, 20 rounds (matches JAX threefry2x32_p)
__device__ __forceinline__ void threefry2x32(uint32_t k0, uint32_t k1,
                                             uint32_t x0, uint32_t x1,
                                             uint32_t& o0, uint32_t& o1) {
    uint32_t k2 = k0 ^ k1 ^ 0x1BD11BDAu;
#define TF_RND(r) { x0 += x1; x1 = rotl32(x1, (r)); x1 ^= x0; }
    x0 += k0; x1 += k1;
    TF_RND(13) TF_RND(15) TF_RND(26) TF_RND(6)
    x0 += k1; x1 += k2 + 1u;
    TF_RND(17) TF_RND(29) TF_RND(16) TF_RND(24)
    x0 += k2; x1 += k0 + 2u;
    TF_RND(13) TF_RND(15) TF_RND(26) TF_RND(6)
    x0 += k0; x1 += k1 + 3u;
    TF_RND(17) TF_RND(29) TF_RND(16) TF_RND(24)
    x0 += k1; x1 += k2 + 4u;
    TF_RND(13) TF_RND(15) TF_RND(26) TF_RND(6)
    x0 += k2; x1 += k0 + 5u;
#undef TF_RND
    o0 = x0; o1 = x1;
}

// ---------------------------------------------------------------------------
// Kernel A: blocks [0,16): JAX permutation inverse map.
//           blocks [16, 16+256): fused depthwise-3x3 + pointwise partials,
//           24 channels/block, double-buffered 4-plane batches (MLP=4),
//           1 barrier per 4 channels.
// ---------------------------------------------------------------------------
__global__ __launch_bounds__(256)
void patch_vote_kA(const float* __restrict__ feature,
                   const float* __restrict__ dww,
                   const float* __restrict__ pww) {
    int tid = threadIdx.x;

    if (blockIdx.x < NPERMBLK) {
        // ---- permutation block (verified exact) ----
        __shared__ __align__(16) uint32_t bits[NUNSEL];   // 1004 = 251 * 4
        uint32_t s0, s1;
        threefry2x32(0u, 42u, 0u, 1u, s0, s1);
        for (int i = tid; i < NUNSEL; i += 256) {
            uint32_t b1, b2;
            threefry2x32(s0, s1, 0u, (uint32_t)i, b1, b2);
            bits[i] = b1 ^ b2;
        }
        __syncthreads();

        int e = tid >> 2, part = tid & 3;
        int idx = blockIdx.x * ELEM_PER_PB + e;
        int rank = 0;
        bool valid = (e < ELEM_PER_PB) && (idx < NUNSEL);
        if (valid) {
            uint32_t bi = bits[idx];
            int q4b = part * 63;
            int q4e = q4b + 63; if (q4e > 251) q4e = 251;
            const uint4* b4 = reinterpret_cast<const uint4*>(bits);
            for (int q4 = q4b; q4 < q4e; q4++) {
                uint4 v = b4[q4];
                int q = q4 * 4;
                rank += (v.x < bi) || (v.x == bi && (q    ) < idx);
                rank += (v.y < bi) || (v.y == bi && (q + 1) < idx);
                rank += (v.z < bi) || (v.z == bi && (q + 2) < idx);
                rank += (v.w < bi) || (v.w == bi && (q + 3) < idx);
            }
        }
        rank += __shfl_xor_sync(0xffffffffu, rank, 1);
        rank += __shfl_xor_sync(0xffffffffu, rank, 2);
        if (valid && part == 0)
            g_invperm[idx] = (rank < NREM) ? rank : -1;
        return;
    }

    // ---- conv block ----
    int id    = blockIdx.x - NPERMBLK;
    int img   = id >> 4;          // / NCHUNK
    int chunk = id & 15;
    int c0    = chunk * CHPER;

    __shared__ __align__(16) float planes[2][4][PLSZ];
    __shared__ float wsm[CHPER * 10];

    for (int i = tid; i < 2 * 4 * PLSZ; i += 256)
        (&planes[0][0][0])[i] = 0.f;
    for (int i = tid; i < CHPER * 10; i += 256) {
        int ch = i / 10, k = i - ch * 10;
        wsm[i] = (k < 9) ? __ldg(dww + (size_t)(c0 + ch) * 9 + k)
                         : __ldg(pww + c0 + ch);
    }

    // 2x2 output tile per thread
    int tx = tid & 15, ty = tid >> 4;
    int px = tx * 2, py = ty * 2;

    // float4 global load -> smem mapping
    int lp = tid * 4;
    int ly = lp >> 5, lx = lp & 31;
    int dstoff = (ly + 1) * PLROW + lx + 1;

    const float4* f4 = reinterpret_cast<const float4*>(
        feature + ((size_t)img * CCH + c0) * NPIX);

    float4 v0, v1, v2, v3;
    v0 = f4[0 * 256 + tid]; v1 = f4[1 * 256 + tid];
    v2 = f4[2 * 256 + tid]; v3 = f4[3 * 256 + tid];
    __syncthreads();            // zero-init + weights complete
    {
        float* d;
        d = &planes[0][0][dstoff]; d[0]=v0.x; d[1]=v0.y; d[2]=v0.z; d[3]=v0.w;
        d = &planes[0][1][dstoff]; d[0]=v1.x; d[1]=v1.y; d[2]=v1.z; d[3]=v1.w;
        d = &planes[0][2][dstoff]; d[0]=v2.x; d[1]=v2.y; d[2]=v2.z; d[3]=v2.w;
        d = &planes[0][3][dstoff]; d[0]=v3.x; d[1]=v3.y; d[2]=v3.z; d[3]=v3.w;
    }
    v0 = f4[4 * 256 + tid]; v1 = f4[5 * 256 + tid];
    v2 = f4[6 * 256 + tid]; v3 = f4[7 * 256 + tid];
    __syncthreads();            // buffer 0 visible to all

    float acc00 = 0.f, acc01 = 0.f, acc10 = 0.f, acc11 = 0.f;

#pragma unroll
    for (int b = 0; b < NBATCH; b++) {
        int cur = b & 1;
        if (b + 1 < NBATCH) {   // store prefetched batch b+1 into other buffer
            float* d;
            d = &planes[cur^1][0][dstoff]; d[0]=v0.x; d[1]=v0.y; d[2]=v0.z; d[3]=v0.w;
            d = &planes[cur^1][1][dstoff]; d[0]=v1.x; d[1]=v1.y; d[2]=v1.z; d[3]=v1.w;
            d = &planes[cur^1][2][dstoff]; d[0]=v2.x; d[1]=v2.y; d[2]=v2.z; d[3]=v2.w;
            d = &planes[cur^1][3][dstoff]; d[0]=v3.x; d[1]=v3.y; d[2]=v3.z; d[3]=v3.w;
        }
        if (b + 2 < NBATCH) {   // prefetch batch b+2 (4 independent LDG.128)
            int cb = (b + 2) * 4;
            v0 = f4[(cb + 0) * 256 + tid]; v1 = f4[(cb + 1) * 256 + tid];
            v2 = f4[(cb + 2) * 256 + tid]; v3 = f4[(cb + 3) * 256 + tid];
        }

#pragma unroll
        for (int j = 0; j < 4; j++) {
            const float* wp = wsm + (b * 4 + j) * 10;
            float w0 = wp[0], w1 = wp[1], w2 = wp[2];
            float w3 = wp[3], w4 = wp[4], w5 = wp[5];
            float w6 = wp[6], w7 = wp[7], w8 = wp[8];
            float pwc = wp[9];

            // 4x4 patch via 8 aligned float2 loads
            const float2* p2 = reinterpret_cast<const float2*>(
                &planes[cur][j][py * PLROW + px]);
            float2 q00 = p2[0],  q01 = p2[1];
            float2 q10 = p2[18], q11 = p2[19];
            float2 q20 = p2[36], q21 = p2[37];
            float2 q30 = p2[54], q31 = p2[55];
            float a00=q00.x, a01=q00.y, a02=q01.x, a03=q01.y;
            float a10=q10.x, a11=q10.y, a12=q11.x, a13=q11.y;
            float a20=q20.x, a21=q20.y, a22=q21.x, a23=q21.y;
            float a30=q30.x, a31=q30.y, a32=q31.x, a33=q31.y;

            float s00 = w0*a00 + w1*a01 + w2*a02
                      + w3*a10 + w4*a11 + w5*a12
                      + w6*a20 + w7*a21 + w8*a22;
            float s01 = w0*a01 + w1*a02 + w2*a03
                      + w3*a11 + w4*a12 + w5*a13
                      + w6*a21 + w7*a22 + w8*a23;
            float s10 = w0*a10 + w1*a11 + w2*a12
                      + w3*a20 + w4*a21 + w5*a22
                      + w6*a30 + w7*a31 + w8*a32;
            float s11 = w0*a11 + w1*a12 + w2*a13
                      + w3*a21 + w4*a22 + w5*a23
                      + w6*a31 + w7*a32 + w8*a33;

            acc00 = fmaf(pwc, s00, acc00);
            acc01 = fmaf(pwc, s01, acc01);
            acc10 = fmaf(pwc, s10, acc10);
            acc11 = fmaf(pwc, s11, acc11);
        }
        __syncthreads();        // everyone done with planes[cur] & stores
    }

    float2* o2 = reinterpret_cast<float2*>(
        g_partial + (size_t)(chunk * NIMG + img) * NPIX);
    float2 r0; r0.x = acc00; r0.y = acc01;
    float2 r1; r1.x = acc10; r1.y = acc11;
    o2[(py * 32 + px) >> 1]       = r0;
    o2[((py + 1) * 32 + px) >> 1] = r1;
}

// ---------------------------------------------------------------------------
// Kernel B: MLP chunk reduce, per-warp bitonic sort, exact 32-way tournament
//           merge on warp 0 (no threshold), ballot prefix for unselected,
//           invperm gather, float32 outputs.
// ---------------------------------------------------------------------------
__global__ __launch_bounds__(1024)
void patch_vote_kB(float* __restrict__ out) {
    int tid  = threadIdx.x;
    int img  = blockIdx.x;
    int lane = tid & 31, warp = tid >> 5;

    __shared__ unsigned long long s_lists[(KTOP + 1) * 32];  // [rank][warp]
    __shared__ int s_invp[NUNSEL];
    __shared__ int s_flag[NPIX];
    __shared__ int warpcnt[32];

    if (tid < NUNSEL) s_invp[tid] = g_invperm[tid];
    s_flag[tid] = 0;

    // chunk reduction, 4 independent accumulator chains (MLP)
    const float* pp = g_partial + (size_t)img * NPIX + tid;
    float r0 = 0.f, r1 = 0.f, r2 = 0.f, r3 = 0.f;
#pragma unroll
    for (int c = 0; c < NCHUNK; c += 4) {
        r0 += __ldg(pp + (size_t)(c + 0) * NIMG * NPIX);
        r1 += __ldg(pp + (size_t)(c + 1) * NIMG * NPIX);
        r2 += __ldg(pp + (size_t)(c + 2) * NIMG * NPIX);
        r3 += __ldg(pp + (size_t)(c + 3) * NIMG * NPIX);
    }
    float val = (r0 + r1) + (r2 + r3);

    // orderable key: (monotone float bits : 1023 - pix) -> max == JAX order
    uint32_t fb = __float_as_uint(val);
    fb = (fb & 0x80000000u) ? ~fb : (fb | 0x80000000u);
    unsigned long long key =
        ((unsigned long long)fb << 32) | (uint32_t)(NPIX - 1 - tid);

    // per-warp bitonic sort, DESCENDING (lane 0 = max). Keys unique.
#pragma unroll
    for (int k = 2; k <= 32; k <<= 1) {
#pragma unroll
        for (int j = k >> 1; j > 0; j >>= 1) {
            unsigned long long o = __shfl_xor_sync(0xffffffffu, key, j);
            bool dirAsc  = ((lane & k) != 0);
            bool isLower = ((lane & j) == 0);
            bool takeMin = (dirAsc == isLower);
            key = takeMin ? (key < o ? key : o) : (key > o ? key : o);
        }
    }
    // store sorted top-20 column-major; row 20 = sentinel zeros
    if (lane <= KTOP)
        s_lists[lane * 32 + warp] = (lane < KTOP) ? key : 0ull;
    __syncthreads();

    // exact 32-way tournament merge on warp 0: 20 rounds
    if (warp == 0) {
        int h = 0;
        unsigned long long head = s_lists[lane];   // head of list `lane`
        for (int r = 0; r < KTOP; r++) {
            unsigned long long mx = head;
#pragma unroll
            for (int off = 16; off; off >>= 1) {
                unsigned long long o = __shfl_xor_sync(0xffffffffu, mx, off);
                if (o > mx) mx = o;
            }
            if (head == mx) {                      // unique winner
                int pix = NPIX - 1 - (int)(mx & 1023u);
                int X = pix & 31, Y = pix >> 5;
                out[              img * PTOT + r] = (float)(X < 1 ? 1 : X);
                out[NIMG * PTOT + img * PTOT + r] = (float)(Y < 1 ? 1 : Y);
                s_flag[pix] = 1;
                h++;
                head = s_lists[h * 32 + lane];     // h <= 20 -> sentinel row
            }
        }
    }
    __syncthreads();

    // unselected positions via ballot prefix, gather through invperm
    bool sel = (s_flag[tid] != 0);
    unsigned bal = __ballot_sync(0xffffffffu, sel);
    if (lane == 0) warpcnt[warp] = __popc(bal);
    __syncthreads();
    int before = __popc(bal & ((1u << lane) - 1u));
    for (int w2 = 0; w2 < warp; w2++) before += warpcnt[w2];

    if (!sel) {
        int u = tid - before;           // position among unselected (0..1003)
        int j = s_invp[u];
        if (j >= 0) {
            int X = tid & 31, Y = tid >> 5;
            out[              img * PTOT + KTOP + j] = (float)(X < 1 ? 1 : X);
            out[NIMG * PTOT + img * PTOT + KTOP + j] = (float)(Y < 1 ? 1 : Y);
        }
    }
}

extern "C" void kernel_launch(void* const* d_in, const int* in_sizes, int n_in,
                              void* d_out, int out_size) {
    const float* feature = (const float*)d_in[0];
    const float* dww     = (const float*)d_in[1];
    const float* pww     = (const float*)d_in[3];
    float* out = (float*)d_out;

    patch_vote_kA<<<NPERMBLK + NCHUNK * NIMG, 256>>>(feature, dww, pww);
    patch_vote_kB<<<NIMG, 1024>>>(out);
}

// round 7
// speedup vs baseline: 2.9255x; 1.1109x over previous
#include <cuda_runtime.h>
#include <cstdint>

// Problem constants
#define CCH    384
#define NPIX   1024          // 32*32
#define NIMG   16            // only first n=16 rows matter
#define KTOP   20
#define PTOT   96
#define NREM   76            // P - K
#define NUNSEL 1004          // 1024 - 20
#define NCHUNK 16
#define CHPER  24            // 384 / 16
#define NBATCH 6             // 24 channels / 4 per batch
#define NPERMBLK 16
#define ELEM_PER_PB 63       // 16*63 = 1008 >= 1004
#define PLROW  36            // padded row -> aligned float2 reads
#define PLSZ   (PLROW * 34)

// Scratch (device globals: no allocation allowed)
__device__ float g_partial[NCHUNK * NIMG * NPIX];   // [chunk][img][pix]
__device__ int   g_invperm[NUNSEL];

__device__ __forceinline__ uint32_t rotl32(uint32_t x, int d) {
    return (x << d) | (x >> (32 - d));
}

// Threefry-2x32, 20 rounds (matches JAX threefry2x32_p)
__device__ __forceinline__ void threefry2x32(uint32_t k0, uint32_t k1,
                                             uint32_t x0, uint32_t x1,
                                             uint32_t& o0, uint32_t& o1) {
    uint32_t k2 = k0 ^ k1 ^ 0x1BD11BDAu;
#define TF_RND(r) { x0 += x1; x1 = rotl32(x1, (r)); x1 ^= x0; }
    x0 += k0; x1 += k1;
    TF_RND(13) TF_RND(15) TF_RND(26) TF_RND(6)
    x0 += k1; x1 += k2 + 1u;
    TF_RND(17) TF_RND(29) TF_RND(16) TF_RND(24)
    x0 += k2; x1 += k0 + 2u;
    TF_RND(13) TF_RND(15) TF_RND(26) TF_RND(6)
    x0 += k0; x1 += k1 + 3u;
    TF_RND(17) TF_RND(29) TF_RND(16) TF_RND(24)
    x0 += k1; x1 += k2 + 4u;
    TF_RND(13) TF_RND(15) TF_RND(26) TF_RND(6)
    x0 += k2; x1 += k0 + 5u;
#undef TF_RND
    o0 = x0; o1 = x1;
}

// ---------------------------------------------------------------------------
// Kernel A: blocks [0,16): JAX permutation inverse map.
//           blocks [16, 16+256): fused depthwise-3x3 + pointwise partials,
//           24 channels/block, double-buffered 4-plane batches (MLP=4),
//           1 barrier per 4 channels, halo-only zero init.
// ---------------------------------------------------------------------------
__global__ __launch_bounds__(256)
void patch_vote_kA(const float* __restrict__ feature,
                   const float* __restrict__ dww,
                   const float* __restrict__ pww) {
    int tid = threadIdx.x;

    if (blockIdx.x < NPERMBLK) {
        // ---- permutation block (verified exact) ----
        __shared__ __align__(16) uint32_t bits[NUNSEL];   // 1004 = 251 * 4
        uint32_t s0, s1;
        threefry2x32(0u, 42u, 0u, 1u, s0, s1);
        for (int i = tid; i < NUNSEL; i += 256) {
            uint32_t b1, b2;
            threefry2x32(s0, s1, 0u, (uint32_t)i, b1, b2);
            bits[i] = b1 ^ b2;
        }
        __syncthreads();

        int e = tid >> 2, part = tid & 3;
        int idx = blockIdx.x * ELEM_PER_PB + e;
        int rank = 0;
        bool valid = (e < ELEM_PER_PB) && (idx < NUNSEL);
        if (valid) {
            uint32_t bi = bits[idx];
            int q4b = part * 63;
            int q4e = q4b + 63; if (q4e > 251) q4e = 251;
            const uint4* b4 = reinterpret_cast<const uint4*>(bits);
            for (int q4 = q4b; q4 < q4e; q4++) {
                uint4 v = b4[q4];
                int q = q4 * 4;
                rank += (v.x < bi) || (v.x == bi && (q    ) < idx);
                rank += (v.y < bi) || (v.y == bi && (q + 1) < idx);
                rank += (v.z < bi) || (v.z == bi && (q + 2) < idx);
                rank += (v.w < bi) || (v.w == bi && (q + 3) < idx);
            }
        }
        rank += __shfl_xor_sync(0xffffffffu, rank, 1);
        rank += __shfl_xor_sync(0xffffffffu, rank, 2);
        if (valid && part == 0)
            g_invperm[idx] = (rank < NREM) ? rank : -1;
        return;
    }

    // ---- conv block ----
    int id    = blockIdx.x - NPERMBLK;
    int img   = id >> 4;          // / NCHUNK
    int chunk = id & 15;
    int c0    = chunk * CHPER;

    __shared__ __align__(16) float planes[2][4][PLSZ];
    __shared__ float wsm[CHPER * 10];

    // zero only the halo ring (132 cells) of each of the 8 planes
    for (int i = tid; i < 8 * 132; i += 256) {
        int pl = i / 132, r = i - pl * 132;
        int row, col;
        if (r < 34)       { row = 0;            col = r; }
        else if (r < 68)  { row = 33;           col = r - 34; }
        else if (r < 100) { row = 1 + (r - 68); col = 0; }
        else              { row = 1 + (r - 100); col = 33; }
        (&planes[0][0][0])[pl * PLSZ + row * PLROW + col] = 0.f;
    }
    for (int i = tid; i < CHPER * 10; i += 256) {
        int ch = i / 10, k = i - ch * 10;
        wsm[i] = (k < 9) ? __ldg(dww + (size_t)(c0 + ch) * 9 + k)
                         : __ldg(pww + c0 + ch);
    }

    // 2x2 output tile per thread
    int tx = tid & 15, ty = tid >> 4;
    int px = tx * 2, py = ty * 2;

    // float4 global load -> smem mapping
    int lp = tid * 4;
    int ly = lp >> 5, lx = lp & 31;
    int dstoff = (ly + 1) * PLROW + lx + 1;

    const float4* f4 = reinterpret_cast<const float4*>(
        feature + ((size_t)img * CCH + c0) * NPIX);

    float4 v0, v1, v2, v3;
    v0 = f4[0 * 256 + tid]; v1 = f4[1 * 256 + tid];
    v2 = f4[2 * 256 + tid]; v3 = f4[3 * 256 + tid];
    __syncthreads();            // halo zero + weights complete
    {
        float* d;
        d = &planes[0][0][dstoff]; d[0]=v0.x; d[1]=v0.y; d[2]=v0.z; d[3]=v0.w;
        d = &planes[0][1][dstoff]; d[0]=v1.x; d[1]=v1.y; d[2]=v1.z; d[3]=v1.w;
        d = &planes[0][2][dstoff]; d[0]=v2.x; d[1]=v2.y; d[2]=v2.z; d[3]=v2.w;
        d = &planes[0][3][dstoff]; d[0]=v3.x; d[1]=v3.y; d[2]=v3.z; d[3]=v3.w;
    }
    v0 = f4[4 * 256 + tid]; v1 = f4[5 * 256 + tid];
    v2 = f4[6 * 256 + tid]; v3 = f4[7 * 256 + tid];
    __syncthreads();            // buffer 0 visible to all

    float acc00 = 0.f, acc01 = 0.f, acc10 = 0.f, acc11 = 0.f;

#pragma unroll
    for (int b = 0; b < NBATCH; b++) {
        int cur = b & 1;
        if (b + 1 < NBATCH) {   // store prefetched batch b+1 into other buffer
            float* d;
            d = &planes[cur^1][0][dstoff]; d[0]=v0.x; d[1]=v0.y; d[2]=v0.z; d[3]=v0.w;
            d = &planes[cur^1][1][dstoff]; d[0]=v1.x; d[1]=v1.y; d[2]=v1.z; d[3]=v1.w;
            d = &planes[cur^1][2][dstoff]; d[0]=v2.x; d[1]=v2.y; d[2]=v2.z; d[3]=v2.w;
            d = &planes[cur^1][3][dstoff]; d[0]=v3.x; d[1]=v3.y; d[2]=v3.z; d[3]=v3.w;
        }
        if (b + 2 < NBATCH) {   // prefetch batch b+2 (4 independent LDG.128)
            int cb = (b + 2) * 4;
            v0 = f4[(cb + 0) * 256 + tid]; v1 = f4[(cb + 1) * 256 + tid];
            v2 = f4[(cb + 2) * 256 + tid]; v3 = f4[(cb + 3) * 256 + tid];
        }

#pragma unroll
        for (int j = 0; j < 4; j++) {
            const float* wp = wsm + (b * 4 + j) * 10;
            float w0 = wp[0], w1 = wp[1], w2 = wp[2];
            float w3 = wp[3], w4 = wp[4], w5 = wp[5];
            float w6 = wp[6], w7 = wp[7], w8 = wp[8];
            float pwc = wp[9];

            // 4x4 patch via 8 aligned float2 loads
            const float2* p2 = reinterpret_cast<const float2*>(
                &planes[cur][j][py * PLROW + px]);
            float2 q00 = p2[0],  q01 = p2[1];
            float2 q10 = p2[18], q11 = p2[19];
            float2 q20 = p2[36], q21 = p2[37];
            float2 q30 = p2[54], q31 = p2[55];
            float a00=q00.x, a01=q00.y, a02=q01.x, a03=q01.y;
            float a10=q10.x, a11=q10.y, a12=q11.x, a13=q11.y;
            float a20=q20.x, a21=q20.y, a22=q21.x, a23=q21.y;
            float a30=q30.x, a31=q30.y, a32=q31.x, a33=q31.y;

            float s00 = w0*a00 + w1*a01 + w2*a02
                      + w3*a10 + w4*a11 + w5*a12
                      + w6*a20 + w7*a21 + w8*a22;
            float s01 = w0*a01 + w1*a02 + w2*a03
                      + w3*a11 + w4*a12 + w5*a13
                      + w6*a21 + w7*a22 + w8*a23;
            float s10 = w0*a10 + w1*a11 + w2*a12
                      + w3*a20 + w4*a21 + w5*a22
                      + w6*a30 + w7*a31 + w8*a32;
            float s11 = w0*a11 + w1*a12 + w2*a13
                      + w3*a21 + w4*a22 + w5*a23
                      + w6*a31 + w7*a32 + w8*a33;

            acc00 = fmaf(pwc, s00, acc00);
            acc01 = fmaf(pwc, s01, acc01);
            acc10 = fmaf(pwc, s10, acc10);
            acc11 = fmaf(pwc, s11, acc11);
        }
        __syncthreads();        // everyone done with planes[cur] & stores
    }

    float2* o2 = reinterpret_cast<float2*>(
        g_partial + (size_t)(chunk * NIMG + img) * NPIX);
    float2 r0; r0.x = acc00; r0.y = acc01;
    float2 r1; r1.x = acc10; r1.y = acc11;
    o2[(py * 32 + px) >> 1]       = r0;
    o2[((py + 1) * 32 + px) >> 1] = r1;
}

// ---------------------------------------------------------------------------
// Kernel B: full-MLP chunk reduce, per-warp bitonic sort, exact 32-way
//           tournament merge with REDUX max, scan-based unselected prefix,
//           invperm gather, float32 outputs.
// ---------------------------------------------------------------------------
__global__ __launch_bounds__(1024)
void patch_vote_kB(float* __restrict__ out) {
    int tid  = threadIdx.x;
    int img  = blockIdx.x;
    int lane = tid & 31, warp = tid >> 5;

    __shared__ unsigned long long s_lists[(KTOP + 1) * 32];  // [rank][warp]
    __shared__ int s_invp[NUNSEL];
    __shared__ int s_flag[NPIX];
    __shared__ int warpcnt[32];

    if (tid < NUNSEL) s_invp[tid] = g_invperm[tid];
    s_flag[tid] = 0;

    // chunk reduction: 16 fully independent loads, pairwise tree sum
    const float* pp = g_partial + (size_t)img * NPIX + tid;
    float a[NCHUNK];
#pragma unroll
    for (int c = 0; c < NCHUNK; c++)
        a[c] = __ldg(pp + (size_t)c * NIMG * NPIX);
#pragma unroll
    for (int s = 1; s < NCHUNK; s <<= 1)
#pragma unroll
        for (int c = 0; c < NCHUNK; c += 2 * s)
            a[c] += a[c + s];
    float val = a[0];

    // orderable key: (monotone float bits : 1023 - pix) -> max == JAX order
    uint32_t fb = __float_as_uint(val);
    fb = (fb & 0x80000000u) ? ~fb : (fb | 0x80000000u);
    unsigned long long key =
        ((unsigned long long)fb << 32) | (uint32_t)(NPIX - 1 - tid);

    // per-warp bitonic sort, DESCENDING (lane 0 = max). Keys unique.
#pragma unroll
    for (int k = 2; k <= 32; k <<= 1) {
#pragma unroll
        for (int j = k >> 1; j > 0; j >>= 1) {
            unsigned long long o = __shfl_xor_sync(0xffffffffu, key, j);
            bool dirAsc  = ((lane & k) != 0);
            bool isLower = ((lane & j) == 0);
            bool takeMin = (dirAsc == isLower);
            key = takeMin ? (key < o ? key : o) : (key > o ? key : o);
        }
    }
    // store sorted top-20 column-major; row 20 = sentinel zeros
    if (lane <= KTOP)
        s_lists[lane * 32 + warp] = (lane < KTOP) ? key : 0ull;
    __syncthreads();

    // exact 32-way tournament merge on warp 0, REDUX-based rounds
    if (warp == 0) {
        int h = 0;
        unsigned long long head = s_lists[lane];   // head of list `lane`
        for (int r = 0; r < KTOP; r++) {
            uint32_t hi = (uint32_t)(head >> 32);
            uint32_t lo = (uint32_t)head;
            uint32_t m1 = __reduce_max_sync(0xffffffffu, hi);
            uint32_t lo2 = (hi == m1) ? lo : 0u;
            uint32_t m2 = __reduce_max_sync(0xffffffffu, lo2);
            if (hi == m1 && lo == m2) {            // unique winner
                int pix = NPIX - 1 - (int)(lo & 1023u);
                int X = pix & 31, Y = pix >> 5;
                out[              img * PTOT + r] = (float)(X < 1 ? 1 : X);
                out[NIMG * PTOT + img * PTOT + r] = (float)(Y < 1 ? 1 : Y);
                s_flag[pix] = 1;
                h++;
                head = s_lists[h * 32 + lane];     // h <= 20 -> sentinel row
            }
        }
    }
    __syncthreads();

    // unselected positions via ballot + warp-0 scan of warp counts
    bool sel = (s_flag[tid] != 0);
    unsigned bal = __ballot_sync(0xffffffffu, sel);
    if (lane == 0) warpcnt[warp] = __popc(bal);
    __syncthreads();
    if (warp == 0) {
        int v = warpcnt[lane], s = v;
#pragma unroll
        for (int off = 1; off < 32; off <<= 1) {
            int o = __shfl_up_sync(0xffffffffu, s, off);
            if (lane >= off) s += o;
        }
        warpcnt[lane] = s - v;      // exclusive prefix
    }
    __syncthreads();
    int before = warpcnt[warp] + __popc(bal & ((1u << lane) - 1u));

    if (!sel) {
        int u = tid - before;           // position among unselected (0..1003)
        int j = s_invp[u];
        if (j >= 0) {
            int X = tid & 31, Y = tid >> 5;
            out[              img * PTOT + KTOP + j] = (float)(X < 1 ? 1 : X);
            out[NIMG * PTOT + img * PTOT + KTOP + j] = (float)(Y < 1 ? 1 : Y);
        }
    }
}

extern "C" void kernel_launch(void* const* d_in, const int* in_sizes, int n_in,
                              void* d_out, int out_size) {
    const float* feature = (const float*)d_in[0];
    const float* dww     = (const float*)d_in[1];
    const float* pww     = (const float*)d_in[3];
    float* out = (float*)d_out;

    patch_vote_kA<<<NPERMBLK + NCHUNK * NIMG, 256>>>(feature, dww, pww);
    patch_vote_kB<<<NIMG, 1024>>>(out);
}